// round 2
// baseline (speedup 1.0000x reference)
#include <cuda_runtime.h>
#include <math.h>

#define Bsz 64
#define Vv  50000
#define Ee  512
#define Hh  1024
#define LQv 32
#define LDv 400

// ---------------- scratch (static device allocations; no cudaMalloc) ----------------
__device__ float g_embedded[Bsz * Ee];
__device__ float g_qh[Bsz * Hh];
__device__ float g_ehq[LQv * Bsz * Hh];
__device__ float g_scoreq[Bsz * LQv];
__device__ float g_ctxq[Bsz * Hh];
__device__ float g_dqh[Bsz * Hh];
__device__ float g_ehd[(size_t)LDv * Bsz * Hh];   // ~105 MB
__device__ float g_ctxd[Bsz * Hh];
__device__ float g_gates[Bsz * 4 * Hh];
__device__ float g_dgates[Bsz * 4 * Hh];
__device__ float g_xout[Bsz * 2 * Hh];

// ---------------- reductions ----------------
__device__ __forceinline__ float warp_reduce_sum(float v) {
#pragma unroll
    for (int o = 16; o > 0; o >>= 1) v += __shfl_xor_sync(0xffffffffu, v, o);
    return v;
}
__device__ __forceinline__ float warp_reduce_max(float v) {
#pragma unroll
    for (int o = 16; o > 0; o >>= 1) v = fmaxf(v, __shfl_xor_sync(0xffffffffu, v, o));
    return v;
}

__device__ float block_reduce_sum(float v) {
    __shared__ float sm[32];
    int tid = threadIdx.x, lane = tid & 31, w = tid >> 5;
    __syncthreads();
    v = warp_reduce_sum(v);
    if (lane == 0) sm[w] = v;
    __syncthreads();
    int nw = (blockDim.x + 31) >> 5;
    v = (tid < nw) ? sm[tid] : 0.f;
    if (w == 0) v = warp_reduce_sum(v);
    if (tid == 0) sm[0] = v;
    __syncthreads();
    return sm[0];
}

__device__ float block_reduce_max(float v) {
    __shared__ float sm[32];
    int tid = threadIdx.x, lane = tid & 31, w = tid >> 5;
    __syncthreads();
    v = warp_reduce_max(v);
    if (lane == 0) sm[w] = v;
    __syncthreads();
    int nw = (blockDim.x + 31) >> 5;
    v = (tid < nw) ? sm[tid] : -3.0e38f;
    if (w == 0) v = warp_reduce_max(v);
    if (tid == 0) sm[0] = v;
    __syncthreads();
    return sm[0];
}

// ---------------- tiled SGEMM:  C[M,N] (+)= A[M,K] * B[N,K]^T ----------------
// A row-major (lda), B row-major (ldb) treated as N rows of length K, C row-major (ldc).
#define BM 128
#define BN 128
#define BK 8
#define TM 8
#define TN 8

__global__ __launch_bounds__(256) void sgemm_nt(
    const float* __restrict__ A, int lda,
    const float* __restrict__ B, int ldb,
    float* __restrict__ C, int ldc,
    int M, int N, int K, int accumulate)
{
    __shared__ float As[BK][BM];
    __shared__ float Bs[BK][BN];

    int tid = threadIdx.x;                 // 256 threads
    int block_row = blockIdx.y * BM;
    int block_col = blockIdx.x * BN;

    int tx = tid & 15;                     // 0..15
    int ty = tid >> 4;                     // 0..15

    int ld_row  = tid >> 1;                // 0..127
    int ld_col4 = (tid & 1) * 4;           // 0 or 4

    float acc[TM][TN];
#pragma unroll
    for (int i = 0; i < TM; i++)
#pragma unroll
        for (int j = 0; j < TN; j++) acc[i][j] = 0.f;

    for (int k0 = 0; k0 < K; k0 += BK) {
        // load A tile (128 x 8)
        {
            int gm = block_row + ld_row;
            float4 v = make_float4(0.f, 0.f, 0.f, 0.f);
            if (gm < M) v = *(const float4*)(A + (size_t)gm * lda + k0 + ld_col4);
            As[ld_col4 + 0][ld_row] = v.x;
            As[ld_col4 + 1][ld_row] = v.y;
            As[ld_col4 + 2][ld_row] = v.z;
            As[ld_col4 + 3][ld_row] = v.w;
        }
        // load B tile (128 x 8)
        {
            int gn = block_col + ld_row;
            float4 v = make_float4(0.f, 0.f, 0.f, 0.f);
            if (gn < N) v = *(const float4*)(B + (size_t)gn * ldb + k0 + ld_col4);
            Bs[ld_col4 + 0][ld_row] = v.x;
            Bs[ld_col4 + 1][ld_row] = v.y;
            Bs[ld_col4 + 2][ld_row] = v.z;
            Bs[ld_col4 + 3][ld_row] = v.w;
        }
        __syncthreads();

#pragma unroll
        for (int k = 0; k < BK; k++) {
            float ra[TM], rb[TN];
#pragma unroll
            for (int i = 0; i < TM; i++) ra[i] = As[k][ty * TM + i];
#pragma unroll
            for (int j = 0; j < TN; j++) rb[j] = Bs[k][tx * TN + j];
#pragma unroll
            for (int i = 0; i < TM; i++)
#pragma unroll
                for (int j = 0; j < TN; j++) acc[i][j] = fmaf(ra[i], rb[j], acc[i][j]);
        }
        __syncthreads();
    }

#pragma unroll
    for (int i = 0; i < TM; i++) {
        int gm = block_row + ty * TM + i;
        if (gm >= M) continue;
#pragma unroll
        for (int j = 0; j < TN; j++) {
            int gn = block_col + tx * TN + j;
            if (gn >= N) continue;
            size_t idx = (size_t)gm * ldc + gn;
            C[idx] = (accumulate ? C[idx] : 0.f) + acc[i][j];
        }
    }
}

// ---------------- embedding gather ----------------
__global__ void embed_kernel(const int* __restrict__ input,
                             const float* __restrict__ embed,
                             float* __restrict__ out)
{
    int b = blockIdx.x;
    int e = threadIdx.x;                    // 512 threads
    out[b * Ee + e] = embed[(size_t)input[b] * Ee + e];
}

// ---------------- attention score:  score[b,t] = sum_j v[j]*tanh(eh[m,j]+qh[b,j]+bias[j]) ----------------
__global__ __launch_bounds__(256) void score_kernel(
    const float* __restrict__ eh, const float* __restrict__ qh,
    const float* __restrict__ bias, const float* __restrict__ v,
    float* __restrict__ score, int T)
{
    int m = blockIdx.x;            // m = t*B + b  (matches [T,B,H] flattening)
    int t = m / Bsz;
    int b = m % Bsz;
    const float* e = eh + (size_t)m * Hh;
    const float* q = qh + (size_t)b * Hh;
    float s = 0.f;
    for (int j = threadIdx.x; j < Hh; j += blockDim.x)
        s += v[j] * tanhf(e[j] + q[j] + bias[j]);
    s = block_reduce_sum(s);
    if (threadIdx.x == 0) score[b * T + t] = s;
}

// ---------------- in-place row softmax on [B, T] ----------------
__global__ __launch_bounds__(128) void softmax_kernel(float* __restrict__ s, int T)
{
    float* x = s + (size_t)blockIdx.x * T;
    float m = -3.0e38f;
    for (int t = threadIdx.x; t < T; t += blockDim.x) m = fmaxf(m, x[t]);
    m = block_reduce_max(m);
    float sum = 0.f;
    for (int t = threadIdx.x; t < T; t += blockDim.x) sum += expf(x[t] - m);
    sum = block_reduce_sum(sum);
    float inv = 1.f / sum;
    for (int t = threadIdx.x; t < T; t += blockDim.x) x[t] = expf(x[t] - m) * inv;
}

// ---------------- weighted context:  ctx[b,h] = sum_t w[b,t] * enc[t,b,h] ----------------
__global__ __launch_bounds__(256) void ctx_kernel(
    const float* __restrict__ w, const float* __restrict__ enc,
    float* __restrict__ ctx, int T)
{
    __shared__ float ws[LDv];
    int b = blockIdx.y;
    int h = blockIdx.x * blockDim.x + threadIdx.x;
    for (int t = threadIdx.x; t < T; t += blockDim.x) ws[t] = w[(size_t)b * T + t];
    __syncthreads();
    float acc = 0.f;
    for (int t = 0; t < T; t++)
        acc = fmaf(ws[t], enc[((size_t)t * Bsz + b) * Hh + h], acc);
    ctx[(size_t)b * Hh + h] = acc;
}

// ---------------- LSTM gates -> (h, c) ----------------
__global__ __launch_bounds__(256) void lstm_kernel(
    const float* __restrict__ gates, const float* __restrict__ bi,
    const float* __restrict__ bh, const float* __restrict__ cprev,
    float* __restrict__ hout, float* __restrict__ cout)
{
    int idx = blockIdx.x * blockDim.x + threadIdx.x;
    if (idx >= Bsz * Hh) return;
    int b = idx >> 10;
    int j = idx & (Hh - 1);
    const float* g = gates + (size_t)b * 4 * Hh;
    float gi = g[j]           + bi[j]           + bh[j];
    float gf = g[Hh + j]      + bi[Hh + j]      + bh[Hh + j];
    float gg = g[2 * Hh + j]  + bi[2 * Hh + j]  + bh[2 * Hh + j];
    float go = g[3 * Hh + j]  + bi[3 * Hh + j]  + bh[3 * Hh + j];
    float si = 1.f / (1.f + expf(-gi));
    float sf = 1.f / (1.f + expf(-gf));
    float so = 1.f / (1.f + expf(-go));
    float c = sf * cprev[idx] + si * tanhf(gg);
    cout[idx] = c;
    hout[idx] = so * tanhf(c);
}

// ---------------- concat [B,H]+[B,H] -> [B,2H] ----------------
__global__ void concat2_kernel(const float* __restrict__ a,
                               const float* __restrict__ b,
                               float* __restrict__ out)
{
    int idx = blockIdx.x * blockDim.x + threadIdx.x;
    if (idx >= Bsz * 2 * Hh) return;
    int bb = idx >> 11;
    int j  = idx & (2 * Hh - 1);
    out[idx] = (j < Hh) ? a[(size_t)bb * Hh + j] : b[(size_t)bb * Hh + (j - Hh)];
}

// ---------------- in-place log_softmax over V (adds bias first) ----------------
__global__ __launch_bounds__(512) void logsoftmax_kernel(
    float* __restrict__ logits, const float* __restrict__ bias)
{
    float* x = logits + (size_t)blockIdx.x * Vv;
    int tid = threadIdx.x;
    float m = -3.0e38f;
    for (int v = tid; v < Vv; v += blockDim.x) m = fmaxf(m, x[v] + bias[v]);
    m = block_reduce_max(m);
    float s = 0.f;
    for (int v = tid; v < Vv; v += blockDim.x) s += expf(x[v] + bias[v] - m);
    s = block_reduce_sum(s);
    float lse = m + logf(s);
    for (int v = tid; v < Vv; v += blockDim.x) x[v] = x[v] + bias[v] - lse;
}

// ---------------- host ----------------
static inline void gemm(const float* A, int lda, const float* B, int ldb,
                        float* C, int ldc, int M, int N, int K, int acc)
{
    dim3 grid((N + BN - 1) / BN, (M + BM - 1) / BM);
    sgemm_nt<<<grid, 256>>>(A, lda, B, ldb, C, ldc, M, N, K, acc);
}

extern "C" void kernel_launch(void* const* d_in, const int* in_sizes, int n_in,
                              void* d_out, int out_size)
{
    const int*   input = (const int*)  d_in[0];
    const float* h0    = (const float*)d_in[1];
    const float* c0    = (const float*)d_in[2];
    const float* dh0   = (const float*)d_in[3];
    const float* dc0   = (const float*)d_in[4];
    const float* qenc  = (const float*)d_in[5];   // [LQ,B,H]
    const float* denc  = (const float*)d_in[6];   // [LD,B,H]
    const float* embed = (const float*)d_in[7];
    const float* W_qa  = (const float*)d_in[8];   // [H, 2H]
    const float* b_qa  = (const float*)d_in[9];
    const float* v_q   = (const float*)d_in[10];
    const float* W_da  = (const float*)d_in[11];  // [H, 3H]
    const float* b_da  = (const float*)d_in[12];
    const float* v_d   = (const float*)d_in[13];
    const float* W_ih  = (const float*)d_in[14];  // [4H, H+E]
    const float* W_hh  = (const float*)d_in[15];  // [4H, H]
    const float* b_ih  = (const float*)d_in[16];
    const float* b_hh  = (const float*)d_in[17];
    const float* Wd_ih = (const float*)d_in[18];  // [4H, H]
    const float* Wd_hh = (const float*)d_in[19];  // [4H, H]
    const float* bd_ih = (const float*)d_in[20];
    const float* bd_hh = (const float*)d_in[21];
    const float* W_out = (const float*)d_in[22];  // [V, 2H]
    const float* b_out = (const float*)d_in[23];

    float* out        = (float*)d_out;
    float* out_logits = out;                               // [B,V]
    float* out_h1     = out + (size_t)Bsz * Vv;            // [B,H]
    float* out_c1     = out_h1 + (size_t)Bsz * Hh;
    float* out_dh     = out_c1 + (size_t)Bsz * Hh;
    float* out_dc     = out_dh + (size_t)Bsz * Hh;
    float* out_docw   = out_dc + (size_t)Bsz * Hh;         // [B,LD]

    float *p_emb, *p_qh, *p_ehq, *p_scoreq, *p_ctxq, *p_dqh, *p_ehd, *p_ctxd,
          *p_gates, *p_dgates, *p_xout;
    cudaGetSymbolAddress((void**)&p_emb,    g_embedded);
    cudaGetSymbolAddress((void**)&p_qh,     g_qh);
    cudaGetSymbolAddress((void**)&p_ehq,    g_ehq);
    cudaGetSymbolAddress((void**)&p_scoreq, g_scoreq);
    cudaGetSymbolAddress((void**)&p_ctxq,   g_ctxq);
    cudaGetSymbolAddress((void**)&p_dqh,    g_dqh);
    cudaGetSymbolAddress((void**)&p_ehd,    g_ehd);
    cudaGetSymbolAddress((void**)&p_ctxd,   g_ctxd);
    cudaGetSymbolAddress((void**)&p_gates,  g_gates);
    cudaGetSymbolAddress((void**)&p_dgates, g_dgates);
    cudaGetSymbolAddress((void**)&p_xout,   g_xout);

    // 1) embedding gather
    embed_kernel<<<Bsz, Ee>>>(input, embed, p_emb);

    // 2) query attention
    gemm(h0, Hh,   W_qa,      2 * Hh, p_qh,  Hh, Bsz,       Hh, Hh, 0);   // h-part
    gemm(qenc, Hh, W_qa + Hh, 2 * Hh, p_ehq, Hh, LQv * Bsz, Hh, Hh, 0);   // enc-part
    score_kernel<<<LQv * Bsz, 256>>>(p_ehq, p_qh, b_qa, v_q, p_scoreq, LQv);
    softmax_kernel<<<Bsz, 128>>>(p_scoreq, LQv);
    ctx_kernel<<<dim3(Hh / 256, Bsz), 256>>>(p_scoreq, qenc, p_ctxq, LQv);

    // 3) doc attention (query = [h_last, q_ctx])
    gemm(h0, Hh,     W_da,          3 * Hh, p_dqh, Hh, Bsz, Hh, Hh, 0);
    gemm(p_ctxq, Hh, W_da + Hh,     3 * Hh, p_dqh, Hh, Bsz, Hh, Hh, 1);
    gemm(denc, Hh,   W_da + 2 * Hh, 3 * Hh, p_ehd, Hh, LDv * Bsz, Hh, Hh, 0);
    score_kernel<<<LDv * Bsz, 256>>>(p_ehd, p_dqh, b_da, v_d, out_docw, LDv);
    softmax_kernel<<<Bsz, 128>>>(out_docw, LDv);
    ctx_kernel<<<dim3(Hh / 256, Bsz), 256>>>(out_docw, denc, p_ctxd, LDv);

    // 4) distraction LSTM cell
    gemm(p_ctxd, Hh, Wd_ih, Hh, p_dgates, 4 * Hh, Bsz, 4 * Hh, Hh, 0);
    gemm(dh0,    Hh, Wd_hh, Hh, p_dgates, 4 * Hh, Bsz, 4 * Hh, Hh, 1);
    lstm_kernel<<<(Bsz * Hh + 255) / 256, 256>>>(p_dgates, bd_ih, bd_hh, dc0, out_dh, out_dc);

    // 5) main LSTM cell: rnn_in = [embedded(E), doc_ctx(H)]
    gemm(p_emb, Ee,  W_ih,      Hh + Ee, p_gates, 4 * Hh, Bsz, 4 * Hh, Ee, 0);
    gemm(p_ctxd, Hh, W_ih + Ee, Hh + Ee, p_gates, 4 * Hh, Bsz, 4 * Hh, Hh, 1);
    gemm(h0, Hh,     W_hh,      Hh,      p_gates, 4 * Hh, Bsz, 4 * Hh, Hh, 1);
    lstm_kernel<<<(Bsz * Hh + 255) / 256, 256>>>(p_gates, b_ih, b_hh, c0, out_h1, out_c1);

    // 6) output projection + log_softmax
    concat2_kernel<<<(Bsz * 2 * Hh + 255) / 256, 256>>>(out_h1, p_ctxd, p_xout);
    gemm(p_xout, 2 * Hh, W_out, 2 * Hh, out_logits, Vv, Bsz, Vv, 2 * Hh, 0);
    logsoftmax_kernel<<<Bsz, 512>>>(out_logits, b_out);
}

// round 4
// speedup vs baseline: 4.8248x; 4.8248x over previous
#include <cuda_runtime.h>
#include <cuda_bf16.h>
#include <stdint.h>
#include <math.h>

#define Bsz 64
#define Vv  50000
#define Ee  512
#define Hh  1024
#define LQv 32
#define LDv 400

// ---------------- scratch (static device allocations; no cudaMalloc) ----------------
__device__ float g_embedded[Bsz * Ee];
__device__ float g_qh[Bsz * Hh];
__device__ float g_scoreq[Bsz * LQv];
__device__ float g_ctxq[Bsz * Hh];
__device__ float g_dq[Bsz * 2 * Hh];
__device__ float g_dqh[Bsz * Hh];
__device__ float g_ctxd[Bsz * Hh];
__device__ float g_gates[Bsz * 4 * Hh];
__device__ float g_dgates[Bsz * 4 * Hh];
__device__ float g_rnn[Bsz * (Hh + Ee)];
__device__ float g_xout[Bsz * 2 * Hh];

// ================= HMMA bf16 split-precision GEMM =================
// C[M,N] = A[M,K] * B[N,K]^T  with ~fp32 precision (bf16 hi/lo, 3 products).
// mode 0: C = R;  mode 1: C += R;
// mode 2: score[b,t] += sum_col v[col]*tanh(R + qadd[b*N+col] + bias[col]),
//         row = t*Bsz + b.  (no C write)
//
// Block tile 128x128, K-slab 32. 8 warps, warp tile 64x32 (4x4 m16n8 tiles).
// Smem layout: row-major [128][40] bf16 (stride 40 => conflict-free frag loads).

#define SSTR 40

__device__ __forceinline__ void mma16816(float* d, const uint32_t* a, const uint32_t* b) {
    asm volatile(
        "mma.sync.aligned.m16n8k16.row.col.f32.bf16.bf16.f32 "
        "{%0,%1,%2,%3}, {%4,%5,%6,%7}, {%8,%9}, {%0,%1,%2,%3};"
        : "+f"(d[0]), "+f"(d[1]), "+f"(d[2]), "+f"(d[3])
        : "r"(a[0]), "r"(a[1]), "r"(a[2]), "r"(a[3]), "r"(b[0]), "r"(b[1]));
}

__device__ __forceinline__ void cvt_store(uint16_t* hi, uint16_t* lo, int off, float4 v) {
    __nv_bfloat162 h01 = __floats2bfloat162_rn(v.x, v.y);
    __nv_bfloat162 h23 = __floats2bfloat162_rn(v.z, v.w);
    float2 f01 = __bfloat1622float2(h01);
    float2 f23 = __bfloat1622float2(h23);
    __nv_bfloat162 l01 = __floats2bfloat162_rn(v.x - f01.x, v.y - f01.y);
    __nv_bfloat162 l23 = __floats2bfloat162_rn(v.z - f23.x, v.w - f23.y);
    *(uint2*)(hi + off) = make_uint2(*(uint32_t*)&h01, *(uint32_t*)&h23);
    *(uint2*)(lo + off) = make_uint2(*(uint32_t*)&l01, *(uint32_t*)&l23);
}

__global__ __launch_bounds__(256, 1) void hgemm(
    const float* __restrict__ A, int lda,
    const float* __restrict__ B, int ldb,
    float* __restrict__ C, int ldc,
    int M, int N, int K, int mode,
    const float* __restrict__ qadd, const float* __restrict__ bias,
    const float* __restrict__ vvec, float* __restrict__ score, int T)
{
    __shared__ __align__(16) uint16_t smem[4][128 * SSTR];
    uint16_t* Ah = smem[0];
    uint16_t* Al = smem[1];
    uint16_t* Bh = smem[2];
    uint16_t* Bl = smem[3];

    int tid  = threadIdx.x;
    int lane = tid & 31;
    int w    = tid >> 5;
    int g    = lane >> 2;      // 0..7
    int tg   = lane & 3;       // 0..3
    int wm   = w >> 2;         // 0..1
    int wn   = w & 3;          // 0..3

    int mrow0 = blockIdx.y * 128;
    int nrow0 = blockIdx.x * 128;

    int r0 = tid >> 3;          // 0..31
    int c4 = (tid & 7) << 2;    // 0,4,..,28 (float offset in 32-wide slab)

    float acc[4][4][4];
#pragma unroll
    for (int i = 0; i < 4; i++)
#pragma unroll
        for (int j = 0; j < 4; j++)
#pragma unroll
            for (int q = 0; q < 4; q++) acc[i][j][q] = 0.f;

    const float4 Z4 = make_float4(0.f, 0.f, 0.f, 0.f);
    float4 va[4], vb[4];
    // prefetch slab 0
#pragma unroll
    for (int it = 0; it < 4; it++) {
        int rr = r0 + it * 32;
        int gm = mrow0 + rr, gn = nrow0 + rr;
        va[it] = (gm < M) ? *(const float4*)(A + (size_t)gm * lda + c4) : Z4;
        vb[it] = (gn < N) ? *(const float4*)(B + (size_t)gn * ldb + c4) : Z4;
    }

    int ns = K >> 5;
    for (int s = 0; s < ns; s++) {
        // store current slab to smem (convert fp32 -> bf16 hi/lo)
#pragma unroll
        for (int it = 0; it < 4; it++) {
            int rr = r0 + it * 32;
            cvt_store(Ah, Al, rr * SSTR + c4, va[it]);
            cvt_store(Bh, Bl, rr * SSTR + c4, vb[it]);
        }
        __syncthreads();

        // prefetch next slab (overlaps with MMA below)
        if (s + 1 < ns) {
            int k0 = (s + 1) << 5;
#pragma unroll
            for (int it = 0; it < 4; it++) {
                int rr = r0 + it * 32;
                int gm = mrow0 + rr, gn = nrow0 + rr;
                va[it] = (gm < M) ? *(const float4*)(A + (size_t)gm * lda + k0 + c4) : Z4;
                vb[it] = (gn < N) ? *(const float4*)(B + (size_t)gn * ldb + k0 + c4) : Z4;
            }
        }

#pragma unroll
        for (int ks = 0; ks < 32; ks += 16) {
            uint32_t ah[4][4], al_[4][4], bh[4][2], bl_[4][2];
#pragma unroll
            for (int i = 0; i < 4; i++) {
                int base = (wm * 64 + i * 16 + g) * SSTR + ks + tg * 2;
                ah[i][0]  = *(const uint32_t*)(Ah + base);
                ah[i][1]  = *(const uint32_t*)(Ah + base + 8 * SSTR);
                ah[i][2]  = *(const uint32_t*)(Ah + base + 8);
                ah[i][3]  = *(const uint32_t*)(Ah + base + 8 * SSTR + 8);
                al_[i][0] = *(const uint32_t*)(Al + base);
                al_[i][1] = *(const uint32_t*)(Al + base + 8 * SSTR);
                al_[i][2] = *(const uint32_t*)(Al + base + 8);
                al_[i][3] = *(const uint32_t*)(Al + base + 8 * SSTR + 8);
            }
#pragma unroll
            for (int j = 0; j < 4; j++) {
                int nb = (wn * 32 + j * 8 + g) * SSTR + ks + tg * 2;
                bh[j][0]  = *(const uint32_t*)(Bh + nb);
                bh[j][1]  = *(const uint32_t*)(Bh + nb + 8);
                bl_[j][0] = *(const uint32_t*)(Bl + nb);
                bl_[j][1] = *(const uint32_t*)(Bl + nb + 8);
            }
            // 16 independent tiles per pass -> good HMMA pipelining
#pragma unroll
            for (int i = 0; i < 4; i++)
#pragma unroll
                for (int j = 0; j < 4; j++) mma16816(acc[i][j], ah[i], bh[j]);
#pragma unroll
            for (int i = 0; i < 4; i++)
#pragma unroll
                for (int j = 0; j < 4; j++) mma16816(acc[i][j], ah[i], bl_[j]);
#pragma unroll
            for (int i = 0; i < 4; i++)
#pragma unroll
                for (int j = 0; j < 4; j++) mma16816(acc[i][j], al_[i], bh[j]);
        }
        __syncthreads();
    }

    // ---------------- epilogue ----------------
    if (mode == 2) {
#pragma unroll
        for (int i = 0; i < 4; i++) {
            int r1 = mrow0 + wm * 64 + i * 16 + g;
            int r2 = r1 + 8;
            int b1 = r1 & (Bsz - 1), t1 = r1 >> 6;
            int b2 = r2 & (Bsz - 1), t2 = r2 >> 6;
            float p1 = 0.f, p2 = 0.f;
#pragma unroll
            for (int j = 0; j < 4; j++) {
#pragma unroll
                for (int c = 0; c < 2; c++) {
                    int col = nrow0 + wn * 32 + j * 8 + tg * 2 + c;
                    float vv = vvec[col], bb = bias[col];
                    p1 = fmaf(vv, tanhf(acc[i][j][c]     + qadd[(size_t)b1 * N + col] + bb), p1);
                    p2 = fmaf(vv, tanhf(acc[i][j][2 + c] + qadd[(size_t)b2 * N + col] + bb), p2);
                }
            }
            p1 += __shfl_xor_sync(0xffffffffu, p1, 1);
            p1 += __shfl_xor_sync(0xffffffffu, p1, 2);
            p2 += __shfl_xor_sync(0xffffffffu, p2, 1);
            p2 += __shfl_xor_sync(0xffffffffu, p2, 2);
            if (tg == 0) {
                atomicAdd(&score[b1 * T + t1], p1);
                atomicAdd(&score[b2 * T + t2], p2);
            }
        }
    } else {
#pragma unroll
        for (int i = 0; i < 4; i++) {
            int r1 = mrow0 + wm * 64 + i * 16 + g;
            int r2 = r1 + 8;
#pragma unroll
            for (int j = 0; j < 4; j++) {
                int col = nrow0 + wn * 32 + j * 8 + tg * 2;
                if (r1 < M) {
                    size_t ix = (size_t)r1 * ldc + col;
                    if (col < N)     C[ix]     = (mode ? C[ix]     : 0.f) + acc[i][j][0];
                    if (col + 1 < N) C[ix + 1] = (mode ? C[ix + 1] : 0.f) + acc[i][j][1];
                }
                if (r2 < M) {
                    size_t ix = (size_t)r2 * ldc + col;
                    if (col < N)     C[ix]     = (mode ? C[ix]     : 0.f) + acc[i][j][2];
                    if (col + 1 < N) C[ix + 1] = (mode ? C[ix + 1] : 0.f) + acc[i][j][3];
                }
            }
        }
    }
}

// ================= elementwise / reduction kernels =================
__device__ __forceinline__ float warp_reduce_sum(float v) {
#pragma unroll
    for (int o = 16; o > 0; o >>= 1) v += __shfl_xor_sync(0xffffffffu, v, o);
    return v;
}
__device__ __forceinline__ float warp_reduce_max(float v) {
#pragma unroll
    for (int o = 16; o > 0; o >>= 1) v = fmaxf(v, __shfl_xor_sync(0xffffffffu, v, o));
    return v;
}
__device__ float block_reduce_sum(float v) {
    __shared__ float sm[32];
    int tid = threadIdx.x, lane = tid & 31, w = tid >> 5;
    __syncthreads();
    v = warp_reduce_sum(v);
    if (lane == 0) sm[w] = v;
    __syncthreads();
    int nw = (blockDim.x + 31) >> 5;
    v = (tid < nw) ? sm[tid] : 0.f;
    if (w == 0) v = warp_reduce_sum(v);
    if (tid == 0) sm[0] = v;
    __syncthreads();
    return sm[0];
}
__device__ float block_reduce_max(float v) {
    __shared__ float sm[32];
    int tid = threadIdx.x, lane = tid & 31, w = tid >> 5;
    __syncthreads();
    v = warp_reduce_max(v);
    if (lane == 0) sm[w] = v;
    __syncthreads();
    int nw = (blockDim.x + 31) >> 5;
    v = (tid < nw) ? sm[tid] : -3.0e38f;
    if (w == 0) v = warp_reduce_max(v);
    if (tid == 0) sm[0] = v;
    __syncthreads();
    return sm[0];
}

__global__ void embed_kernel(const int* __restrict__ input,
                             const float* __restrict__ embed,
                             float* __restrict__ out)
{
    int b = blockIdx.x;
    int e = threadIdx.x;
    out[b * Ee + e] = embed[(size_t)input[b] * Ee + e];
}

__global__ __launch_bounds__(128) void softmax_kernel(float* __restrict__ s, int T)
{
    float* x = s + (size_t)blockIdx.x * T;
    float m = -3.0e38f;
    for (int t = threadIdx.x; t < T; t += blockDim.x) m = fmaxf(m, x[t]);
    m = block_reduce_max(m);
    float sum = 0.f;
    for (int t = threadIdx.x; t < T; t += blockDim.x) sum += expf(x[t] - m);
    sum = block_reduce_sum(sum);
    float inv = 1.f / sum;
    for (int t = threadIdx.x; t < T; t += blockDim.x) x[t] = expf(x[t] - m) * inv;
}

__global__ __launch_bounds__(256) void ctx_kernel(
    const float* __restrict__ w, const float* __restrict__ enc,
    float* __restrict__ ctx, int T)
{
    __shared__ float ws[LDv];
    int b = blockIdx.y;
    int h = blockIdx.x * blockDim.x + threadIdx.x;
    for (int t = threadIdx.x; t < T; t += blockDim.x) ws[t] = w[(size_t)b * T + t];
    __syncthreads();
    float acc = 0.f;
    for (int t = 0; t < T; t++)
        acc = fmaf(ws[t], enc[((size_t)t * Bsz + b) * Hh + h], acc);
    ctx[(size_t)b * Hh + h] = acc;
}

__global__ __launch_bounds__(256) void lstm_kernel(
    const float* __restrict__ gates, const float* __restrict__ bi,
    const float* __restrict__ bh, const float* __restrict__ cprev,
    float* __restrict__ hout, float* __restrict__ cout)
{
    int idx = blockIdx.x * blockDim.x + threadIdx.x;
    if (idx >= Bsz * Hh) return;
    int b = idx >> 10;
    int j = idx & (Hh - 1);
    const float* g = gates + (size_t)b * 4 * Hh;
    float gi = g[j]          + bi[j]          + bh[j];
    float gf = g[Hh + j]     + bi[Hh + j]     + bh[Hh + j];
    float gg = g[2 * Hh + j] + bi[2 * Hh + j] + bh[2 * Hh + j];
    float go = g[3 * Hh + j] + bi[3 * Hh + j] + bh[3 * Hh + j];
    float si = 1.f / (1.f + expf(-gi));
    float sf = 1.f / (1.f + expf(-gf));
    float so = 1.f / (1.f + expf(-go));
    float c = sf * cprev[idx] + si * tanhf(gg);
    cout[idx] = c;
    hout[idx] = so * tanhf(c);
}

__global__ void concat2k(const float* __restrict__ a, int wa,
                         const float* __restrict__ b, int wb,
                         float* __restrict__ o, int rows)
{
    int W = wa + wb;
    int idx = blockIdx.x * blockDim.x + threadIdx.x;
    if (idx >= rows * W) return;
    int r = idx / W, j = idx - r * W;
    o[idx] = (j < wa) ? a[(size_t)r * wa + j] : b[(size_t)r * wb + (j - wa)];
}

__global__ __launch_bounds__(512) void logsoftmax_kernel(
    float* __restrict__ logits, const float* __restrict__ bias)
{
    float* x = logits + (size_t)blockIdx.x * Vv;
    int tid = threadIdx.x;
    float m = -3.0e38f;
    for (int v = tid; v < Vv; v += blockDim.x) m = fmaxf(m, x[v] + bias[v]);
    m = block_reduce_max(m);
    float s = 0.f;
    for (int v = tid; v < Vv; v += blockDim.x) s += expf(x[v] + bias[v] - m);
    s = block_reduce_sum(s);
    float lse = m + logf(s);
    for (int v = tid; v < Vv; v += blockDim.x) x[v] = x[v] + bias[v] - lse;
}

// ================= host =================
static inline void tcg(const float* A, int lda, const float* B, int ldb,
                       float* C, int ldc, int M, int N, int K, int mode,
                       const float* qadd = nullptr, const float* bias = nullptr,
                       const float* vvec = nullptr, float* score = nullptr, int T = 0)
{
    dim3 grid((N + 127) / 128, (M + 127) / 128);
    hgemm<<<grid, 256>>>(A, lda, B, ldb, C, ldc, M, N, K, mode,
                         qadd, bias, vvec, score, T);
}

extern "C" void kernel_launch(void* const* d_in, const int* in_sizes, int n_in,
                              void* d_out, int out_size)
{
    const int*   input = (const int*)  d_in[0];
    const float* h0    = (const float*)d_in[1];
    const float* c0    = (const float*)d_in[2];
    const float* dh0   = (const float*)d_in[3];
    const float* dc0   = (const float*)d_in[4];
    const float* qenc  = (const float*)d_in[5];   // [LQ,B,H]
    const float* denc  = (const float*)d_in[6];   // [LD,B,H]
    const float* embed = (const float*)d_in[7];
    const float* W_qa  = (const float*)d_in[8];   // [H, 2H]
    const float* b_qa  = (const float*)d_in[9];
    const float* v_q   = (const float*)d_in[10];
    const float* W_da  = (const float*)d_in[11];  // [H, 3H]
    const float* b_da  = (const float*)d_in[12];
    const float* v_d   = (const float*)d_in[13];
    const float* W_ih  = (const float*)d_in[14];  // [4H, H+E]
    const float* W_hh  = (const float*)d_in[15];  // [4H, H]
    const float* b_ih  = (const float*)d_in[16];
    const float* b_hh  = (const float*)d_in[17];
    const float* Wd_ih = (const float*)d_in[18];  // [4H, H]
    const float* Wd_hh = (const float*)d_in[19];  // [4H, H]
    const float* bd_ih = (const float*)d_in[20];
    const float* bd_hh = (const float*)d_in[21];
    const float* W_out = (const float*)d_in[22];  // [V, 2H]
    const float* b_out = (const float*)d_in[23];

    float* out        = (float*)d_out;
    float* out_logits = out;                               // [B,V]
    float* out_h1     = out + (size_t)Bsz * Vv;            // [B,H]
    float* out_c1     = out_h1 + (size_t)Bsz * Hh;
    float* out_dh     = out_c1 + (size_t)Bsz * Hh;
    float* out_dc     = out_dh + (size_t)Bsz * Hh;
    float* out_docw   = out_dc + (size_t)Bsz * Hh;         // [B,LD]

    float *p_emb, *p_qh, *p_scoreq, *p_ctxq, *p_dq, *p_dqh, *p_ctxd,
          *p_gates, *p_dgates, *p_rnn, *p_xout;
    cudaGetSymbolAddress((void**)&p_emb,    g_embedded);
    cudaGetSymbolAddress((void**)&p_qh,     g_qh);
    cudaGetSymbolAddress((void**)&p_scoreq, g_scoreq);
    cudaGetSymbolAddress((void**)&p_ctxq,   g_ctxq);
    cudaGetSymbolAddress((void**)&p_dq,     g_dq);
    cudaGetSymbolAddress((void**)&p_dqh,    g_dqh);
    cudaGetSymbolAddress((void**)&p_ctxd,   g_ctxd);
    cudaGetSymbolAddress((void**)&p_gates,  g_gates);
    cudaGetSymbolAddress((void**)&p_dgates, g_dgates);
    cudaGetSymbolAddress((void**)&p_rnn,    g_rnn);
    cudaGetSymbolAddress((void**)&p_xout,   g_xout);

    // 1) embedding gather
    embed_kernel<<<Bsz, Ee>>>(input, embed, p_emb);

    // 2) query attention: qh = h_last @ W_qa[:, :H]^T ; fused energy+score over qenc
    cudaMemsetAsync(p_scoreq, 0, Bsz * LQv * sizeof(float));
    tcg(h0, Hh, W_qa, 2 * Hh, p_qh, Hh, Bsz, Hh, Hh, 0);
    tcg(qenc, Hh, W_qa + Hh, 2 * Hh, nullptr, 0, LQv * Bsz, Hh, Hh, 2,
        p_qh, b_qa, v_q, p_scoreq, LQv);
    softmax_kernel<<<Bsz, 128>>>(p_scoreq, LQv);
    ctx_kernel<<<dim3(Hh / 256, Bsz), 256>>>(p_scoreq, qenc, p_ctxq, LQv);

    // 3) doc attention: dqh = [h_last, q_ctx] @ W_da[:, :2H]^T ; fused score over denc
    concat2k<<<(Bsz * 2 * Hh + 255) / 256, 256>>>(h0, Hh, p_ctxq, Hh, p_dq, Bsz);
    tcg(p_dq, 2 * Hh, W_da, 3 * Hh, p_dqh, Hh, Bsz, Hh, 2 * Hh, 0);
    cudaMemsetAsync(out_docw, 0, Bsz * LDv * sizeof(float));
    tcg(denc, Hh, W_da + 2 * Hh, 3 * Hh, nullptr, 0, LDv * Bsz, Hh, Hh, 2,
        p_dqh, b_da, v_d, out_docw, LDv);
    softmax_kernel<<<Bsz, 128>>>(out_docw, LDv);
    ctx_kernel<<<dim3(Hh / 256, Bsz), 256>>>(out_docw, denc, p_ctxd, LDv);

    // 4) distraction LSTM cell
    tcg(p_ctxd, Hh, Wd_ih, Hh, p_dgates, 4 * Hh, Bsz, 4 * Hh, Hh, 0);
    tcg(dh0,    Hh, Wd_hh, Hh, p_dgates, 4 * Hh, Bsz, 4 * Hh, Hh, 1);
    lstm_kernel<<<(Bsz * Hh + 255) / 256, 256>>>(p_dgates, bd_ih, bd_hh, dc0, out_dh, out_dc);

    // 5) main LSTM cell: rnn_in = [embedded(E), doc_ctx(H)]
    concat2k<<<(Bsz * (Hh + Ee) + 255) / 256, 256>>>(p_emb, Ee, p_ctxd, Hh, p_rnn, Bsz);
    tcg(p_rnn, Hh + Ee, W_ih, Hh + Ee, p_gates, 4 * Hh, Bsz, 4 * Hh, Hh + Ee, 0);
    tcg(h0,    Hh,      W_hh, Hh,      p_gates, 4 * Hh, Bsz, 4 * Hh, Hh, 1);
    lstm_kernel<<<(Bsz * Hh + 255) / 256, 256>>>(p_gates, b_ih, b_hh, c0, out_h1, out_c1);

    // 6) output projection + log_softmax
    concat2k<<<(Bsz * 2 * Hh + 255) / 256, 256>>>(out_h1, Hh, p_ctxd, Hh, p_xout, Bsz);
    tcg(p_xout, 2 * Hh, W_out, 2 * Hh, out_logits, Vv, Bsz, Vv, 2 * Hh, 0);
    logsoftmax_kernel<<<Bsz, 512>>>(out_logits, b_out);
}